// round 12
// baseline (speedup 1.0000x reference)
#include <cuda_runtime.h>
#include <math_constants.h>
#include <cfloat>

// Problem constants (B=2, L=256, A=12, C=32, K=30)
#define NB 2
#define NL 256
#define NA 12
#define NATOM 3072          // NL*NA
#define NROWS (NB*NATOM)    // 6144
#define NC 32
#define KNB 30
#define BIGD 1000000.0f
#define EMPTY_BITS 0xFFFFFFFFu
#define POISON 1.0e18f               // masked-atom coordinate (d2 -> 3e36 exactly)
#define FULL 0xffffffffu

// Output layout (all float32, concatenated in reference tuple order)
#define O_COORDS 0                       // (B, NATOM, 3)  -> 18432
#define O_MASK   (NB*NATOM*3)            // (B, NATOM)     -> 6144
#define O_ENC    (O_MASK + NB*NATOM)     // (B, NATOM, 32) -> 196608
#define O_DIST   (O_ENC + NB*NATOM*NC)   // (B, NATOM, 30) -> 184320
#define O_IDX    (O_DIST + NB*NATOM*KNB) // (B, NATOM, 30) -> 184320

#define WARPS 4              // warps per block; each warp handles 2 rows
#define THR (WARPS * 32)     // 128

__device__ float4 g_atoms[NB * NATOM];   // poisoned {x,y,z,mask}, 98 KB
__device__ float  g_A[NB * NC];          // rstd * scale
__device__ float  g_B[NB * NC];          // shift - mean * rstd * scale
__device__ int    g_rows[NROWS];         // compacted: active rows first
__device__ int    g_nact;                // number of active rows (multiple of 12)

// ---------------------------------------------------------------------------
// Prep: block 0 computes coefs + row compaction; all blocks poison atoms.
// ---------------------------------------------------------------------------
#define PREP_BLOCKS 48
__global__ void prep_kernel(const float* __restrict__ coords,
                            const int* __restrict__ mask,
                            const float* __restrict__ T,
                            const float* __restrict__ scale,
                            const float* __restrict__ shift) {
    int tid = threadIdx.x;     // 256

    if (blockIdx.x == 0) {
        // ---- graph-norm coefficients ----
        __shared__ float sred[NB][8];
        int warp = tid >> 5, lane = tid & 31;
        int s0 = __reduce_add_sync(FULL, mask[tid]);
        int s1 = __reduce_add_sync(FULL, mask[NL + tid]);
        if (lane == 0) { sred[0][warp] = (float)s0; sred[1][warp] = (float)s1; }
        __syncthreads();
        if (tid < NB * NC) {
            int b = tid >> 5, c = tid & 31;
            float nm = 0.f;
            #pragma unroll
            for (int i = 0; i < 8; ++i) nm += sred[b][i];
            float colsum = 0.f, tv[NA];
            #pragma unroll
            for (int a = 0; a < NA; ++a) { tv[a] = T[a * NC + c]; colsum += tv[a]; }
            float cntA = nm * (float)NA;
            float cnt  = fmaxf(cntA, 1.0f);
            float mean = (nm * colsum) / cnt;
            float ssqm = 0.f;
            #pragma unroll
            for (int a = 0; a < NA; ++a) {
                float d = tv[a] - mean;
                ssqm = fmaf(d, d, ssqm);
            }
            float ssq  = nm * ssqm + ((float)NATOM - cntA) * mean * mean;
            float rstd = rsqrtf(ssq / cnt + 1e-5f);
            float Ac   = rstd * scale[c];
            g_A[tid] = Ac;
            g_B[tid] = shift[c] - mean * Ac;
        }

        // ---- row compaction: scan over 512 residues (2 per thread) ----
        __shared__ int buf[2][256];
        int r0 = 2 * tid, r1 = 2 * tid + 1;
        int m0 = mask[r0];
        int m1 = mask[r1];
        int pairsum = m0 + m1;
        buf[0][tid] = pairsum;
        __syncthreads();
        int src = 0;
        #pragma unroll
        for (int off = 1; off < 256; off <<= 1) {
            int v = buf[src][tid] + ((tid >= off) ? buf[src][tid - off] : 0);
            buf[1 - src][tid] = v;
            src ^= 1;
            __syncthreads();
        }
        int incl = buf[src][tid];             // inclusive prefix of pair sums
        int nA = buf[src][255];               // total active residues
        if (tid == 0) g_nact = nA * NA;

        int pre0 = incl - pairsum;            // exclusive prefix at residue r0
        int pre1 = pre0 + m0;
        int base0 = m0 ? (NA * pre0) : (NA * (nA + (r0 - pre0)));
        int base1 = m1 ? (NA * pre1) : (NA * (nA + (r1 - pre1)));
        #pragma unroll
        for (int a = 0; a < NA; ++a) {
            g_rows[base0 + a] = r0 * NA + a;
            g_rows[base1 + a] = r1 * NA + a;
        }
    }

    // ---- all blocks: poison atoms ----
    for (int a = blockIdx.x * 256 + tid; a < NROWS; a += PREP_BLOCKS * 256) {
        int b = a / NATOM;
        int j = a - b * NATOM;
        int m = mask[b * NL + j / NA];
        float4 v;
        float x = coords[a * 3 + 0], y = coords[a * 3 + 1], z = coords[a * 3 + 2];
        v.x = m ? x : POISON;
        v.y = m ? y : POISON;
        v.z = m ? z : POISON;
        v.w = (float)m;
        g_atoms[a] = v;
    }
}

// ---------------------------------------------------------------------------
// Refill: k-th smallest of the 48-element sub-column [tb,tb+48) of column w.
// q is warp-uniform. Valid result on all lanes.
// ---------------------------------------------------------------------------
__device__ __forceinline__ void refill48(const float4* At, int lane, int w,
                                         int tb, int k,
                                         float qx, float qy, float qz,
                                         unsigned &resv, int &resj) {
    int t0 = tb + lane;
    float4 a0 = __ldg(&At[t0 * 32 + w]);
    float dx = qx - a0.x, dy = qy - a0.y, dz = qz - a0.z;
    unsigned k0 = __float_as_uint(fmaf(dx, dx, fmaf(dy, dy, dz * dz)));
    int j0 = t0 * 32 + w;
    unsigned k1; int j1;
    if (lane < 16) {
        int t1 = tb + 32 + lane;
        float4 a1 = __ldg(&At[t1 * 32 + w]);
        float ex = qx - a1.x, ey = qy - a1.y, ez = qz - a1.z;
        k1 = __float_as_uint(fmaf(ex, ex, fmaf(ey, ey, ez * ez)));
        j1 = t1 * 32 + w;
    } else { k1 = EMPTY_BITS; j1 = -1; }

    resv = EMPTY_BITS; resj = 0;
    for (int it = 0; it < k; ++it) {
        unsigned lmin = (k1 < k0) ? k1 : k0;   // strict: prefer j0 (lower) on tie
        int      lj   = (k1 < k0) ? j1 : j0;
        unsigned gm  = __reduce_min_sync(FULL, lmin);
        unsigned gcj = (lmin == gm) ? (unsigned)lj : 0xFFFFFFFFu;
        unsigned gj  = __reduce_min_sync(FULL, gcj);
        resv = gm; resj = (int)gj;
        if (j0 == (int)gj) k0 = EMPTY_BITS;
        if (j1 == (int)gj) k1 = EMPTY_BITS;
    }
}

// ---------------------------------------------------------------------------
// KNN: each warp handles TWO compacted row slots (2u, 2u+1). One atom load
// serves both rows' distances; the two selection chains interleave.
// Zero smem; single wave (768 blocks, 6/SM).
// ---------------------------------------------------------------------------
__global__ void __launch_bounds__(THR, 6)
knn_kernel(const float* __restrict__ coords,
           const float* __restrict__ T,
           float* __restrict__ out) {
    int tid  = threadIdx.x;
    int warp = tid >> 5;
    int lane = tid & 31;

    // coords copy + mask output, spread over the grid's threads
    {
        int i = blockIdx.x * THR + tid;
        if (i < NROWS * 3) out[O_COORDS + i] = coords[i];
        if (i < NROWS)     out[O_MASK + i] = g_atoms[i].w;
    }

    int u     = blockIdx.x * WARPS + warp;
    int slot0 = 2 * u;
    int nact  = g_nact;
    int row0  = g_rows[slot0];
    int row1g = g_rows[slot0 + 1];

    if (slot0 >= nact) {                      // both rows masked -> constants
        out[O_ENC + row0  * NC + lane] = 0.0f;
        out[O_ENC + row1g * NC + lane] = 0.0f;
        if (lane < KNB) {
            out[O_DIST + row0  * KNB + lane] = BIGD;
            out[O_IDX  + row0  * KNB + lane] = 0.0f;
            out[O_DIST + row1g * KNB + lane] = BIGD;
            out[O_IDX  + row1g * KNB + lane] = 0.0f;
        }
        return;
    }
    bool act1 = (slot0 + 1 < nact);           // nact is even -> always true here
    int row1 = act1 ? row1g : row0;

    int b   = row0 / NATOM;                   // pairs never straddle batches
    int ib0 = row0 - b * NATOM;
    int ib1 = row1 - b * NATOM;
    const float4* At = g_atoms + b * NATOM;

    float4 q0 = __ldg(&At[ib0]);
    float4 q1 = __ldg(&At[ib1]);

    // encode (active rows only)
    {
        float Ac = g_A[b * NC + lane], Bc = g_B[b * NC + lane];
        out[O_ENC + row0 * NC + lane] = fmaf(__ldg(&T[(ib0 % NA) * NC + lane]), Ac, Bc);
        if (act1)
            out[O_ENC + row1 * NC + lane] = fmaf(__ldg(&T[(ib1 % NA) * NC + lane]), Ac, Bc);
    }

    // ---- phase A: one load, two rows. Two top-2 streams per lane per row ----
    unsigned va0_0 = EMPTY_BITS, va1_0 = EMPTY_BITS, vb0_0 = EMPTY_BITS, vb1_0 = EMPTY_BITS;
    unsigned va0_1 = EMPTY_BITS, va1_1 = EMPTY_BITS, vb0_1 = EMPTY_BITS, vb1_1 = EMPTY_BITS;
    int ia0_0 = 0, ia1_0 = 0, ib0_0 = 0, ib1_0 = 0;
    int ia0_1 = 0, ia1_1 = 0, ib0_1 = 0, ib1_1 = 0;

    #pragma unroll 4
    for (int t = 0; t < 48; ++t) {
        float4 a = __ldg(&At[t * 32 + lane]);
        int j = t * 32 + lane;
        {
            float dx = q0.x - a.x, dy = q0.y - a.y, dz = q0.z - a.z;
            unsigned kb = __float_as_uint(fmaf(dx, dx, fmaf(dy, dy, dz * dz)));
            bool lt1 = kb < va1_0, lt0 = kb < va0_0;
            va1_0 = lt1 ? (lt0 ? va0_0 : kb) : va1_0;
            ia1_0 = lt1 ? (lt0 ? ia0_0 : j ) : ia1_0;
            va0_0 = lt0 ? kb : va0_0;
            ia0_0 = lt0 ? j  : ia0_0;
        }
        {
            float dx = q1.x - a.x, dy = q1.y - a.y, dz = q1.z - a.z;
            unsigned kb = __float_as_uint(fmaf(dx, dx, fmaf(dy, dy, dz * dz)));
            bool lt1 = kb < va1_1, lt0 = kb < va0_1;
            va1_1 = lt1 ? (lt0 ? va0_1 : kb) : va1_1;
            ia1_1 = lt1 ? (lt0 ? ia0_1 : j ) : ia1_1;
            va0_1 = lt0 ? kb : va0_1;
            ia0_1 = lt0 ? j  : ia0_1;
        }
    }
    #pragma unroll 4
    for (int t = 48; t < 96; ++t) {
        float4 a = __ldg(&At[t * 32 + lane]);
        int j = t * 32 + lane;
        {
            float dx = q0.x - a.x, dy = q0.y - a.y, dz = q0.z - a.z;
            unsigned kb = __float_as_uint(fmaf(dx, dx, fmaf(dy, dy, dz * dz)));
            bool lt1 = kb < vb1_0, lt0 = kb < vb0_0;
            vb1_0 = lt1 ? (lt0 ? vb0_0 : kb) : vb1_0;
            ib1_0 = lt1 ? (lt0 ? ib0_0 : j ) : ib1_0;
            vb0_0 = lt0 ? kb : vb0_0;
            ib0_0 = lt0 ? j  : ib0_0;
        }
        {
            float dx = q1.x - a.x, dy = q1.y - a.y, dz = q1.z - a.z;
            unsigned kb = __float_as_uint(fmaf(dx, dx, fmaf(dy, dy, dz * dz)));
            bool lt1 = kb < vb1_1, lt0 = kb < vb0_1;
            vb1_1 = lt1 ? (lt0 ? vb0_1 : kb) : vb1_1;
            ib1_1 = lt1 ? (lt0 ? ib0_1 : j ) : ib1_1;
            vb0_1 = lt0 ? kb : vb0_1;
            ib0_1 = lt0 ? j  : ib0_1;
        }
    }

    // ---- interleaved extract-min x30 for both rows ----
    int cA_0 = 0, cB_0 = 0, cA_1 = 0, cB_1 = 0;
    unsigned rv0 = 0, rv1 = 0; int rj0 = 0, rj1 = 0;

    #pragma unroll 1
    for (int p = 0; p < KNB; ++p) {
        unsigned pv0 = (vb0_0 < va0_0) ? vb0_0 : va0_0;
        int      pi0 = (vb0_0 < va0_0) ? ib0_0 : ia0_0;
        unsigned pv1 = (vb0_1 < va0_1) ? vb0_1 : va0_1;
        int      pi1 = (vb0_1 < va0_1) ? ib0_1 : ia0_1;

        unsigned m0v = __reduce_min_sync(FULL, pv0);
        unsigned m1v = __reduce_min_sync(FULL, pv1);
        unsigned c0  = (pv0 == m0v) ? (unsigned)pi0 : 0xFFFFFFFFu;
        unsigned c1  = (pv1 == m1v) ? (unsigned)pi1 : 0xFFFFFFFFu;
        unsigned mj0 = __reduce_min_sync(FULL, c0);
        unsigned mj1 = __reduce_min_sync(FULL, c1);
        if (lane == p) { rv0 = m0v; rj0 = (int)mj0; rv1 = m1v; rj1 = (int)mj1; }

        if (p < KNB - 1) {
            int w0 = (int)(mj0 & 31u), tm0 = (int)(mj0 >> 5);
            int w1 = (int)(mj1 & 31u), tm1 = (int)(mj1 >> 5);
            bool fA0 = (tm0 < 48), fA1 = (tm1 < 48);
            bool nr0 = false, nr1 = false;
            if (lane == w0) {
                if (fA0) { va0_0 = va1_0; ia0_0 = ia1_0; va1_0 = EMPTY_BITS; ++cA_0;
                           nr0 = (va0_0 == EMPTY_BITS); }
                else     { vb0_0 = vb1_0; ib0_0 = ib1_0; vb1_0 = EMPTY_BITS; ++cB_0;
                           nr0 = (vb0_0 == EMPTY_BITS); }
            }
            if (lane == w1) {
                if (fA1) { va0_1 = va1_1; ia0_1 = ia1_1; va1_1 = EMPTY_BITS; ++cA_1;
                           nr1 = (va0_1 == EMPTY_BITS); }
                else     { vb0_1 = vb1_1; ib0_1 = ib1_1; vb1_1 = EMPTY_BITS; ++cB_1;
                           nr1 = (vb0_1 == EMPTY_BITS); }
            }
            unsigned bal0 = __ballot_sync(FULL, nr0);
            unsigned bal1 = __ballot_sync(FULL, nr1);
            if (bal0) {
                int k = __shfl_sync(FULL, fA0 ? cA_0 : cB_0, w0) + 1;
                unsigned resv; int resj;
                refill48(At, lane, w0, fA0 ? 0 : 48, k, q0.x, q0.y, q0.z, resv, resj);
                if (lane == w0) {
                    if (fA0) { va0_0 = resv; ia0_0 = resj; }
                    else     { vb0_0 = resv; ib0_0 = resj; }
                }
            }
            if (bal1) {
                int k = __shfl_sync(FULL, fA1 ? cA_1 : cB_1, w1) + 1;
                unsigned resv; int resj;
                refill48(At, lane, w1, fA1 ? 0 : 48, k, q1.x, q1.y, q1.z, resv, resj);
                if (lane == w1) {
                    if (fA1) { va0_1 = resv; ia0_1 = resj; }
                    else     { vb0_1 = resv; ib0_1 = resj; }
                }
            }
        }
    }

    if (lane < KNB) {
        float d20 = __uint_as_float(rv0);
        out[O_DIST + row0 * KNB + lane] = (d20 > 1e30f) ? BIGD : sqrtf(d20 + 1e-6f);
        out[O_IDX  + row0 * KNB + lane] = (float)rj0;
        if (act1) {
            float d21 = __uint_as_float(rv1);
            out[O_DIST + row1 * KNB + lane] = (d21 > 1e30f) ? BIGD : sqrtf(d21 + 1e-6f);
            out[O_IDX  + row1 * KNB + lane] = (float)rj1;
        }
    }
}

// ---------------------------------------------------------------------------
extern "C" void kernel_launch(void* const* d_in, const int* in_sizes, int n_in,
                              void* d_out, int out_size) {
    const float* coords = (const float*)d_in[0];   // (2,256,12,3) f32
    const int*   mask   = (const int*)d_in[1];     // (2,256) i32
    const float* emb    = (const float*)d_in[2];   // (12,32) f32
    const float* scale  = (const float*)d_in[3];   // (1,1,32) f32
    const float* shift  = (const float*)d_in[4];   // (1,1,32) f32
    float* out = (float*)d_out;

    prep_kernel<<<PREP_BLOCKS, 256>>>(coords, mask, emb, scale, shift);

    int nblocks = NROWS / (WARPS * 2);             // 768
    knn_kernel<<<nblocks, THR>>>(coords, emb, out);
}

// round 14
// speedup vs baseline: 1.1722x; 1.1722x over previous
#include <cuda_runtime.h>
#include <math_constants.h>
#include <cfloat>

// Problem constants (B=2, L=256, A=12, C=32, K=30)
#define NB 2
#define NL 256
#define NA 12
#define NATOM 3072          // NL*NA
#define NROWS (NB*NATOM)    // 6144
#define NC 32
#define KNB 30
#define BIGD 1000000.0f
#define EMPTY_BITS 0xFFFFFFFFu
#define POISON 1.0e18f               // masked-atom coordinate (d2 -> 3e36 exactly)
#define FULL 0xffffffffu

// Output layout (all float32, concatenated in reference tuple order)
#define O_COORDS 0                       // (B, NATOM, 3)  -> 18432
#define O_MASK   (NB*NATOM*3)            // (B, NATOM)     -> 6144
#define O_ENC    (O_MASK + NB*NATOM)     // (B, NATOM, 32) -> 196608
#define O_DIST   (O_ENC + NB*NATOM*NC)   // (B, NATOM, 30) -> 184320
#define O_IDX    (O_DIST + NB*NATOM*KNB) // (B, NATOM, 30) -> 184320

#define WARPS 4              // row slots per block (1 row per warp)
#define THR (WARPS * 32)     // 128

__device__ float4 g_atoms[NB * NATOM];   // poisoned {x,y,z,mask}, 98 KB
__device__ float  g_A[NB * NC];          // rstd * scale
__device__ float  g_B[NB * NC];          // shift - mean * rstd * scale
__device__ int    g_rows[NROWS];         // compacted: active rows first
__device__ int    g_nact;                // number of active rows

// ---------------------------------------------------------------------------
// Prep (light): 24 blocks poison atoms (1 atom/thread). Block 0 additionally
// does single-warp shfl-scan compaction (warp 0) and graph-norm coefs.
// ---------------------------------------------------------------------------
#define PREP_BLOCKS 24
__global__ void prep_kernel(const float* __restrict__ coords,
                            const int* __restrict__ mask,
                            const float* __restrict__ T,
                            const float* __restrict__ scale,
                            const float* __restrict__ shift) {
    int tid = threadIdx.x;     // 256

    // ---- poison atoms: exactly 1 atom per thread ----
    {
        int a = blockIdx.x * 256 + tid;     // 24*256 = 6144 = NROWS
        int b = a / NATOM;
        int j = a - b * NATOM;
        int m = mask[b * NL + j / NA];
        float4 v;
        float x = coords[a * 3 + 0], y = coords[a * 3 + 1], z = coords[a * 3 + 2];
        v.x = m ? x : POISON;
        v.y = m ? y : POISON;
        v.z = m ? z : POISON;
        v.w = (float)m;
        g_atoms[a] = v;
    }

    if (blockIdx.x != 0) return;

    __shared__ float s_nm[NB];

    // ---- warp 0: compaction via shfl scan (16 residues per lane) ----
    if (tid < 32) {
        int lane = tid;
        int mloc[16];
        int s = 0;
        #pragma unroll
        for (int i = 0; i < 16; ++i) { mloc[i] = mask[lane * 16 + i]; s += mloc[i]; }
        int incl = s;
        #pragma unroll
        for (int off = 1; off < 32; off <<= 1) {
            int v = __shfl_up_sync(FULL, incl, off);
            if (lane >= off) incl += v;
        }
        int nA  = __shfl_sync(FULL, incl, 31);
        int pre = incl - s;                   // exclusive prefix at residue lane*16
        if (lane == 0)  g_nact = nA * NA;
        if (lane == 16) {                     // single writer for both slots:
            s_nm[0] = (float)pre;             // batch-0 nm = actives in [0,256)
            s_nm[1] = (float)(nA - pre);      // batch-1 nm = remainder
        }

        int r = lane * 16;
        #pragma unroll
        for (int i = 0; i < 16; ++i) {
            int m = mloc[i];
            int base = m ? (NA * pre) : (NA * (nA + (r - pre)));
            #pragma unroll
            for (int a = 0; a < NA; ++a) g_rows[base + a] = r * NA + a;
            pre += m;
            ++r;
        }
    }
    __syncthreads();

    // ---- threads 0-63: graph-norm coefficients ----
    if (tid < NB * NC) {
        int b = tid >> 5, c = tid & 31;
        float nm = s_nm[b];
        float colsum = 0.f, tv[NA];
        #pragma unroll
        for (int a = 0; a < NA; ++a) { tv[a] = T[a * NC + c]; colsum += tv[a]; }
        float cntA = nm * (float)NA;
        float cnt  = fmaxf(cntA, 1.0f);
        float mean = (nm * colsum) / cnt;
        float ssqm = 0.f;
        #pragma unroll
        for (int a = 0; a < NA; ++a) {
            float d = tv[a] - mean;
            ssqm = fmaf(d, d, ssqm);
        }
        float ssq  = nm * ssqm + ((float)NATOM - cntA) * mean * mean;
        float rstd = rsqrtf(ssq / cnt + 1e-5f);
        float Ac   = rstd * scale[c];
        g_A[tid] = Ac;
        g_B[tid] = shift[c] - mean * Ac;
    }
}

// ---------------------------------------------------------------------------
// Refill: k-th smallest of the 48-element sub-column [tb,tb+48) of column w.
// q is warp-uniform. Valid result on all lanes.
// ---------------------------------------------------------------------------
__device__ __forceinline__ void refill48(const float4* At, int lane, int w,
                                         int tb, int k,
                                         float qx, float qy, float qz,
                                         unsigned &resv, int &resj) {
    int t0 = tb + lane;
    float4 a0 = __ldg(&At[t0 * 32 + w]);
    float dx = qx - a0.x, dy = qy - a0.y, dz = qz - a0.z;
    unsigned k0 = __float_as_uint(fmaf(dx, dx, fmaf(dy, dy, dz * dz)));
    int j0 = t0 * 32 + w;
    unsigned k1; int j1;
    if (lane < 16) {
        int t1 = tb + 32 + lane;
        float4 a1 = __ldg(&At[t1 * 32 + w]);
        float ex = qx - a1.x, ey = qy - a1.y, ez = qz - a1.z;
        k1 = __float_as_uint(fmaf(ex, ex, fmaf(ey, ey, ez * ez)));
        j1 = t1 * 32 + w;
    } else { k1 = EMPTY_BITS; j1 = -1; }

    resv = EMPTY_BITS; resj = 0;
    for (int it = 0; it < k; ++it) {
        unsigned lmin = (k1 < k0) ? k1 : k0;   // strict: prefer j0 (lower) on tie
        int      lj   = (k1 < k0) ? j1 : j0;
        unsigned gm  = __reduce_min_sync(FULL, lmin);
        unsigned gcj = (lmin == gm) ? (unsigned)lj : 0xFFFFFFFFu;
        unsigned gj  = __reduce_min_sync(FULL, gcj);
        resv = gm; resj = (int)gj;
        if (j0 == (int)gj) k0 = EMPTY_BITS;
        if (j1 == (int)gj) k1 = EMPTY_BITS;
    }
}

// ---------------------------------------------------------------------------
// KNN: warp-per-slot over compacted rows (R10 engine, cleaned). Zero smem.
// Two branchless top-2 streams per lane; 2 redux per pass; rare gmem refill.
// ---------------------------------------------------------------------------
__global__ void __launch_bounds__(THR, 8)
knn_kernel(const float* __restrict__ coords,
           const float* __restrict__ T,
           float* __restrict__ out) {
    int tid  = threadIdx.x;
    int warp = tid >> 5;
    int lane = tid & 31;

    // coords copy + mask output, grid-stride over spare threads
    {
        int i = blockIdx.x * THR + tid;
        if (i < NROWS * 3) out[O_COORDS + i] = coords[i];
        if (i < NROWS)     out[O_MASK + i] = g_atoms[i].w;
    }

    int slot = blockIdx.x * WARPS + warp;
    int row  = g_rows[slot];
    int b    = row / NATOM;
    int ib   = row - b * NATOM;

    float* dist_out = out + O_DIST + row * KNB;
    float* idx_out  = out + O_IDX  + row * KNB;

    if (slot >= g_nact) {                     // masked row -> constant outputs
        out[O_ENC + row * NC + lane] = 0.0f;
        if (lane < KNB) {
            dist_out[lane] = BIGD;
            idx_out[lane]  = 0.0f;
        }
        return;
    }

    const float4* At = g_atoms + b * NATOM;
    float4 q = __ldg(&At[ib]);

    // encode for active row
    {
        int ty = ib % NA;
        out[O_ENC + row * NC + lane] =
            fmaf(__ldg(&T[ty * NC + lane]), g_A[b * NC + lane], g_B[b * NC + lane]);
    }

    // ---- phase A: two branchless top-2 streams per lane ----
    unsigned va0 = EMPTY_BITS, va1 = EMPTY_BITS, vb0 = EMPTY_BITS, vb1 = EMPTY_BITS;
    int ia0 = 0, ia1 = 0, ib0 = 0, ib1 = 0;

    #pragma unroll 8
    for (int t = 0; t < 48; ++t) {
        float4 a = __ldg(&At[t * 32 + lane]);
        float dx = q.x - a.x, dy = q.y - a.y, dz = q.z - a.z;
        unsigned kb = __float_as_uint(fmaf(dx, dx, fmaf(dy, dy, dz * dz)));
        int j = t * 32 + lane;
        bool lt1 = kb < va1;
        bool lt0 = kb < va0;                  // strict < keeps lowest-index ties
        va1 = lt1 ? (lt0 ? va0 : kb) : va1;
        ia1 = lt1 ? (lt0 ? ia0 : j ) : ia1;
        va0 = lt0 ? kb : va0;
        ia0 = lt0 ? j  : ia0;
    }
    #pragma unroll 8
    for (int t = 48; t < 96; ++t) {
        float4 a = __ldg(&At[t * 32 + lane]);
        float dx = q.x - a.x, dy = q.y - a.y, dz = q.z - a.z;
        unsigned kb = __float_as_uint(fmaf(dx, dx, fmaf(dy, dy, dz * dz)));
        int j = t * 32 + lane;
        bool lt1 = kb < vb1;
        bool lt0 = kb < vb0;
        vb1 = lt1 ? (lt0 ? vb0 : kb) : vb1;
        ib1 = lt1 ? (lt0 ? ib0 : j ) : ib1;
        vb0 = lt0 ? kb : vb0;
        ib0 = lt0 ? j  : ib0;
    }

    int cA = 0, cB = 0;                       // popped counts per stream
    unsigned rvb = 0; int rj = 0;             // lane p holds pass-p result

    #pragma unroll 1
    for (int p = 0; p < KNB; ++p) {
        // presented head = min of two stream heads (tie -> stream A, lower j)
        unsigned pv = (vb0 < va0) ? vb0 : va0;
        int      pi = (vb0 < va0) ? ib0 : ia0;

        unsigned mvb = __reduce_min_sync(FULL, pv);
        unsigned cj  = (pv == mvb) ? (unsigned)pi : 0xFFFFFFFFu;
        unsigned mj  = __reduce_min_sync(FULL, cj);
        if (lane == p) { rvb = mvb; rj = (int)mj; }

        if (p < KNB - 1) {
            int w  = (int)(mj & 31u);
            int tm = (int)(mj >> 5);
            bool fromA = (tm < 48);
            bool needRefill = false;
            if (lane == w) {                  // owner pops the winning stream
                if (fromA) { va0 = va1; ia0 = ia1; va1 = EMPTY_BITS; ++cA;
                             needRefill = (va0 == EMPTY_BITS); }
                else       { vb0 = vb1; ib0 = ib1; vb1 = EMPTY_BITS; ++cB;
                             needRefill = (vb0 == EMPTY_BITS); }
            }
            if (__ballot_sync(FULL, needRefill)) {
                int k = __shfl_sync(FULL, fromA ? cA : cB, w) + 1;
                unsigned resv; int resj;
                refill48(At, lane, w, fromA ? 0 : 48, k, q.x, q.y, q.z, resv, resj);
                if (lane == w) {
                    if (fromA) { va0 = resv; ia0 = resj; }
                    else       { vb0 = resv; ib0 = resj; }
                }
            }
        }
    }

    if (lane < KNB) {
        float d2 = __uint_as_float(rvb);
        float dv = (d2 > 1e30f) ? BIGD : sqrtf(d2 + 1e-6f);
        dist_out[lane] = dv;
        idx_out[lane]  = (float)rj;
    }
}

// ---------------------------------------------------------------------------
extern "C" void kernel_launch(void* const* d_in, const int* in_sizes, int n_in,
                              void* d_out, int out_size) {
    const float* coords = (const float*)d_in[0];   // (2,256,12,3) f32
    const int*   mask   = (const int*)d_in[1];     // (2,256) i32
    const float* emb    = (const float*)d_in[2];   // (12,32) f32
    const float* scale  = (const float*)d_in[3];   // (1,1,32) f32
    const float* shift  = (const float*)d_in[4];   // (1,1,32) f32
    float* out = (float*)d_out;

    prep_kernel<<<PREP_BLOCKS, 256>>>(coords, mask, emb, scale, shift);

    int nblocks = NROWS / WARPS;                   // 1536
    knn_kernel<<<nblocks, THR>>>(coords, emb, out);
}